// round 2
// baseline (speedup 1.0000x reference)
#include <cuda_runtime.h>
#include <cuda_bf16.h>
#include <math.h>

// Problem constants
#define B_   8
#define S1_  4096
#define S2_  256
#define SIP_ 16
#define HID_ 1024
#define H_   16
#define D_   64

// ---------------------------------------------------------------------------
// Scratch: static __device__ globals (no cudaMalloc anywhere, per harness rules)
// ---------------------------------------------------------------------------
__device__ float g_Q   [(size_t)B_ * S1_ * HID_];        // [B,S1,H,D] after LN+RoPE
__device__ float g_KV  [(size_t)B_ * S2_ * 2 * HID_];    // [B,S2,2,H,D], k LN'd in place
__device__ float g_IPKV[(size_t)B_ * SIP_ * 2 * HID_];   // [B,SIP,2,H,D]
__device__ float g_CTX [(size_t)B_ * S1_ * HID_];        // [B,S1,H,D]

// Scratch selector so kernels reference __device__ symbols directly and
// kernel_launch never needs cudaGetSymbolAddress (pure-launch capture path).
__device__ __forceinline__ float* scratch_ptr(int which) {
    switch (which) {
        case 0: return g_Q;
        case 1: return g_KV;
        case 2: return g_IPKV;
        default: return g_CTX;
    }
}

// ---------------------------------------------------------------------------
// SGEMM: C[M,N] = A[M,K] @ B[K,N] + bias[N]  (row-major fp32)
// 128x128 tile, BK=8, 256 threads, 8x8 microtile.
// srcSel/dstSel: -1 = use the passed pointer, else scratch_ptr(index).
// ---------------------------------------------------------------------------
__global__ __launch_bounds__(256) void sgemm128(
    const float* __restrict__ Ain, const float* __restrict__ Bm,
    const float* __restrict__ bias, float* __restrict__ Cout,
    int M, int N, int K, int srcSel, int dstSel)
{
    const float* A = (srcSel < 0) ? Ain : scratch_ptr(srcSel);
    float*       C = (dstSel < 0) ? Cout : scratch_ptr(dstSel);

    __shared__ float As[8][128];
    __shared__ float Bs[8][128];

    const int tid = threadIdx.x;
    const int bx = blockIdx.x;   // N tile
    const int by = blockIdx.y;   // M tile

    const int aRow = tid >> 1;          // 0..127
    const int aCol = (tid & 1) << 2;    // 0 or 4
    const int bRow = tid >> 5;          // 0..7
    const int bCol = (tid & 31) << 2;   // 0..124

    const int tx = tid & 15;            // 0..15 (cols)
    const int ty = tid >> 4;            // 0..15 (rows)

    const float* Ag = A + (size_t)(by * 128 + aRow) * K + aCol;
    const float* Bg = Bm + (size_t)bRow * N + bx * 128 + bCol;

    float acc[8][8];
#pragma unroll
    for (int i = 0; i < 8; i++)
#pragma unroll
        for (int j = 0; j < 8; j++) acc[i][j] = 0.f;

    for (int k0 = 0; k0 < K; k0 += 8) {
        float4 a4 = *(const float4*)(Ag + k0);
        float4 b4 = *(const float4*)(Bg + (size_t)k0 * N);
        As[aCol + 0][aRow] = a4.x;
        As[aCol + 1][aRow] = a4.y;
        As[aCol + 2][aRow] = a4.z;
        As[aCol + 3][aRow] = a4.w;
        *(float4*)&Bs[bRow][bCol] = b4;
        __syncthreads();

#pragma unroll
        for (int k = 0; k < 8; k++) {
            float4 a0 = *(const float4*)&As[k][ty * 8];
            float4 a1 = *(const float4*)&As[k][ty * 8 + 4];
            float4 b0 = *(const float4*)&Bs[k][tx * 8];
            float4 b1 = *(const float4*)&Bs[k][tx * 8 + 4];
            float ar[8] = {a0.x, a0.y, a0.z, a0.w, a1.x, a1.y, a1.z, a1.w};
            float br[8] = {b0.x, b0.y, b0.z, b0.w, b1.x, b1.y, b1.z, b1.w};
#pragma unroll
            for (int i = 0; i < 8; i++)
#pragma unroll
                for (int j = 0; j < 8; j++) acc[i][j] += ar[i] * br[j];
        }
        __syncthreads();
    }

    float4 bias0 = *(const float4*)(bias + bx * 128 + tx * 8);
    float4 bias1 = *(const float4*)(bias + bx * 128 + tx * 8 + 4);

#pragma unroll
    for (int i = 0; i < 8; i++) {
        size_t row = (size_t)(by * 128 + ty * 8 + i);
        float4 c0, c1;
        c0.x = acc[i][0] + bias0.x; c0.y = acc[i][1] + bias0.y;
        c0.z = acc[i][2] + bias0.z; c0.w = acc[i][3] + bias0.w;
        c1.x = acc[i][4] + bias1.x; c1.y = acc[i][5] + bias1.y;
        c1.z = acc[i][6] + bias1.z; c1.w = acc[i][7] + bias1.w;
        float* cp = C + row * N + bx * 128 + tx * 8;
        *(float4*)(cp)     = c0;
        *(float4*)(cp + 4) = c1;
    }
}

// ---------------------------------------------------------------------------
// LayerNorm(D=64) + RoPE on g_Q, in place. One warp per (b,s,h) row.
// ---------------------------------------------------------------------------
__global__ __launch_bounds__(128) void ln_rope_q_kernel(
    const float* __restrict__ w, const float* __restrict__ bb,
    const float* __restrict__ cosb, const float* __restrict__ sinb)
{
    const int row  = blockIdx.x * 4 + (threadIdx.x >> 5);   // 0 .. B*S1*H-1
    const int lane = threadIdx.x & 31;
    const int s    = (row >> 4) & (S1_ - 1);                // row = (b*S1+s)*H + h

    float2* p = (float2*)(g_Q + (size_t)row * 64);
    float2 v = p[lane];

    float sum = v.x + v.y;
#pragma unroll
    for (int o = 16; o; o >>= 1) sum += __shfl_xor_sync(0xffffffffu, sum, o);
    float mu = sum * (1.f / 64.f);

    float dx = v.x - mu, dy = v.y - mu;
    float ss = dx * dx + dy * dy;
#pragma unroll
    for (int o = 16; o; o >>= 1) ss += __shfl_xor_sync(0xffffffffu, ss, o);
    float r = rsqrtf(ss * (1.f / 64.f) + 1e-6f);

    float nx = dx * r * w[2 * lane]     + bb[2 * lane];
    float ny = dy * r * w[2 * lane + 1] + bb[2 * lane + 1];

    float c  = cosb[s * 32 + lane];
    float sn = sinb[s * 32 + lane];
    float2 o2;
    o2.x = nx * c - ny * sn;
    o2.y = nx * sn + ny * c;
    p[lane] = o2;
}

// ---------------------------------------------------------------------------
// LayerNorm(D=64) on the K half of g_KV (sel=1) or g_IPKV (sel=2), in place.
// One warp per (b,s,h). k row at kv[(b*S+s)*2048 + h*64].
// ---------------------------------------------------------------------------
__global__ __launch_bounds__(128) void ln_k_kernel(
    const float* __restrict__ w, const float* __restrict__ bb, int sel)
{
    float* KV = scratch_ptr(sel);
    const int row  = blockIdx.x * 4 + (threadIdx.x >> 5);
    const int lane = threadIdx.x & 31;
    const int h  = row & 15;
    const int bs = row >> 4;

    float2* p = (float2*)(KV + (size_t)bs * 2048 + h * 64);
    float2 v = p[lane];

    float sum = v.x + v.y;
#pragma unroll
    for (int o = 16; o; o >>= 1) sum += __shfl_xor_sync(0xffffffffu, sum, o);
    float mu = sum * (1.f / 64.f);

    float dx = v.x - mu, dy = v.y - mu;
    float ss = dx * dx + dy * dy;
#pragma unroll
    for (int o = 16; o; o >>= 1) ss += __shfl_xor_sync(0xffffffffu, ss, o);
    float r = rsqrtf(ss * (1.f / 64.f) + 1e-6f);

    float2 o2;
    o2.x = dx * r * w[2 * lane]     + bb[2 * lane];
    o2.y = dy * r * w[2 * lane + 1] + bb[2 * lane + 1];
    p[lane] = o2;
}

// ---------------------------------------------------------------------------
// Fused dual attention. Block = 64 queries for one (b,h); 64 threads,
// one query per thread. Flash-style online softmax over key tiles.
// K/V rows strided by 2048 floats ([.,2,H,D] layout).
// ---------------------------------------------------------------------------
template <int KT>
__device__ __forceinline__ void attn_tile(
    const float4 q[16],
    const float* __restrict__ Kbase, const float* __restrict__ Vbase,
    float* Ks, float* Vs, float* Ss, int t,
    float& m, float& l, float acc[64])
{
    if (t < KT) {
        const float4* kp = (const float4*)(Kbase + (size_t)t * 2048);
        const float4* vp = (const float4*)(Vbase + (size_t)t * 2048);
        float4* kd = (float4*)(Ks + t * 64);
        float4* vd = (float4*)(Vs + t * 64);
#pragma unroll
        for (int i = 0; i < 16; i++) { kd[i] = kp[i]; vd[i] = vp[i]; }
    }
    __syncthreads();

    float tmax = -1e30f;
#pragma unroll 2
    for (int j = 0; j < KT; j++) {
        const float4* kr = (const float4*)(Ks + j * 64);
        float s0 = 0.f, s1 = 0.f, s2 = 0.f, s3 = 0.f;
#pragma unroll
        for (int i = 0; i < 4; i++) {
            float4 k0 = kr[4 * i + 0], k1 = kr[4 * i + 1];
            float4 k2 = kr[4 * i + 2], k3 = kr[4 * i + 3];
            float4 q0 = q[4 * i + 0], q1 = q[4 * i + 1];
            float4 q2 = q[4 * i + 2], q3 = q[4 * i + 3];
            s0 += q0.x * k0.x + q0.y * k0.y + q0.z * k0.z + q0.w * k0.w;
            s1 += q1.x * k1.x + q1.y * k1.y + q1.z * k1.z + q1.w * k1.w;
            s2 += q2.x * k2.x + q2.y * k2.y + q2.z * k2.z + q2.w * k2.w;
            s3 += q3.x * k3.x + q3.y * k3.y + q3.z * k3.z + q3.w * k3.w;
        }
        float sc = ((s0 + s1) + (s2 + s3)) * 0.125f;  // 1/sqrt(64)
        Ss[t * 64 + ((j + t) & 63)] = sc;             // swizzled: conflict-free
        tmax = fmaxf(tmax, sc);
    }

    float mn = fmaxf(m, tmax);
    float corr = __expf(m - mn);
    l *= corr;
#pragma unroll
    for (int d = 0; d < 64; d++) acc[d] *= corr;
    m = mn;

#pragma unroll 2
    for (int j = 0; j < KT; j++) {
        float p = __expf(Ss[t * 64 + ((j + t) & 63)] - m);
        l += p;
        const float4* vr = (const float4*)(Vs + j * 64);
#pragma unroll
        for (int i = 0; i < 16; i++) {
            float4 v4 = vr[i];
            acc[4 * i + 0] += p * v4.x;
            acc[4 * i + 1] += p * v4.y;
            acc[4 * i + 2] += p * v4.z;
            acc[4 * i + 3] += p * v4.w;
        }
    }
    __syncthreads();
}

__global__ __launch_bounds__(64) void attn_kernel()
{
    __shared__ float Ks[64 * 64];
    __shared__ float Vs[64 * 64];
    __shared__ float Ss[64 * 64];

    const int qt = blockIdx.x;   // S1/64 tiles
    const int h  = blockIdx.y;
    const int b  = blockIdx.z;
    const int t  = threadIdx.x;

    const size_t qrow = (size_t)(b * S1_ + qt * 64 + t) * H_ + h;
    float4 q[16];
    const float4* qp = (const float4*)(g_Q + qrow * 64);
#pragma unroll
    for (int i = 0; i < 16; i++) q[i] = qp[i];

    float m = -1e30f, l = 0.f, acc[64];
#pragma unroll
    for (int d = 0; d < 64; d++) acc[d] = 0.f;

    // main attention: 256 keys in 4 tiles of 64
    for (int kt = 0; kt < 4; kt++) {
        const float* kb = g_KV + (size_t)(b * S2_ + kt * 64) * 2048 + h * 64;
        attn_tile<64>(q, kb, kb + 1024, Ks, Vs, Ss, t, m, l, acc);
    }
    float inv = 1.f / l;
    float4* cp = (float4*)(g_CTX + qrow * 64);
#pragma unroll
    for (int i = 0; i < 16; i++)
        cp[i] = make_float4(acc[4 * i] * inv, acc[4 * i + 1] * inv,
                            acc[4 * i + 2] * inv, acc[4 * i + 3] * inv);

    // ip attention: 16 keys, separate softmax
    m = -1e30f; l = 0.f;
#pragma unroll
    for (int d = 0; d < 64; d++) acc[d] = 0.f;
    {
        const float* kb = g_IPKV + (size_t)(b * SIP_) * 2048 + h * 64;
        attn_tile<16>(q, kb, kb + 1024, Ks, Vs, Ss, t, m, l, acc);
    }
    inv = 1.f / l;
#pragma unroll
    for (int i = 0; i < 16; i++) {
        float4 c = cp[i];
        c.x += acc[4 * i + 0] * inv;
        c.y += acc[4 * i + 1] * inv;
        c.z += acc[4 * i + 2] * inv;
        c.w += acc[4 * i + 3] * inv;
        cp[i] = c;
    }
}

// ---------------------------------------------------------------------------
// Launch: pure kernel launches only (maximally graph-capture-safe).
// ---------------------------------------------------------------------------
extern "C" void kernel_launch(void* const* d_in, const int* in_sizes, int n_in,
                              void* d_out, int out_size)
{
    const float *x, *y, *ipy, *fcos, *fsin, *wq, *bq, *wkv, *bkv, *wip, *bip;
    const float *qnw, *qnb, *knw, *knb, *ipknw, *ipknb, *wo, *bo;

    if (in_sizes[3] == 131072) {
        // reference-signature order:
        // x,y,ip_y,freqs_cos,freqs_sin,wq,bq,wkv,bkv,w_ip_kv,b_ip_kv,
        // qn_w,qn_b,kn_w,kn_b,ipkn_w,ipkn_b,wo,bo
        x    = (const float*)d_in[0];  y     = (const float*)d_in[1];
        ipy  = (const float*)d_in[2];  fcos  = (const float*)d_in[3];
        fsin = (const float*)d_in[4];  wq    = (const float*)d_in[5];
        bq   = (const float*)d_in[6];  wkv   = (const float*)d_in[7];
        bkv  = (const float*)d_in[8];  wip   = (const float*)d_in[9];
        bip  = (const float*)d_in[10]; qnw   = (const float*)d_in[11];
        qnb  = (const float*)d_in[12]; knw   = (const float*)d_in[13];
        knb  = (const float*)d_in[14]; ipknw = (const float*)d_in[15];
        ipknb= (const float*)d_in[16]; wo    = (const float*)d_in[17];
        bo   = (const float*)d_in[18];
    } else {
        // setup_inputs dict order:
        // x,y,ip_y,wq,bq,wkv,bkv,w_ip_kv,b_ip_kv,qn_w,qn_b,kn_w,kn_b,
        // ipkn_w,ipkn_b,wo,bo,freqs_cos,freqs_sin
        x    = (const float*)d_in[0];  y     = (const float*)d_in[1];
        ipy  = (const float*)d_in[2];  wq    = (const float*)d_in[3];
        bq   = (const float*)d_in[4];  wkv   = (const float*)d_in[5];
        bkv  = (const float*)d_in[6];  wip   = (const float*)d_in[7];
        bip  = (const float*)d_in[8];  qnw   = (const float*)d_in[9];
        qnb  = (const float*)d_in[10]; knw   = (const float*)d_in[11];
        knb  = (const float*)d_in[12]; ipknw = (const float*)d_in[13];
        ipknb= (const float*)d_in[14]; wo    = (const float*)d_in[15];
        bo   = (const float*)d_in[16]; fcos  = (const float*)d_in[17];
        fsin = (const float*)d_in[18];
    }

    const int M1 = B_ * S1_;     // 32768
    const int M2 = B_ * S2_;     // 2048
    const int M3 = B_ * SIP_;    // 128

    // Projections (dst: 0=g_Q, 1=g_KV, 2=g_IPKV, 3=g_CTX)
    sgemm128<<<dim3(HID_ / 128, M1 / 128), 256>>>(x,   wq,  bq,  nullptr, M1, HID_,     HID_, -1, 0);
    sgemm128<<<dim3(2 * HID_ / 128, M2 / 128), 256>>>(y,   wkv, bkv, nullptr, M2, 2 * HID_, HID_, -1, 1);
    sgemm128<<<dim3(2 * HID_ / 128, M3 / 128), 256>>>(ipy, wip, bip, nullptr, M3, 2 * HID_, HID_, -1, 2);

    // Norms + RoPE
    ln_rope_q_kernel<<<(B_ * S1_ * H_) / 4, 128>>>(qnw, qnb, fcos, fsin);
    ln_k_kernel<<<(B_ * S2_ * H_) / 4, 128>>>(knw, knb, 1);
    ln_k_kernel<<<(B_ * SIP_ * H_) / 4, 128>>>(ipknw, ipknb, 2);

    // Dual attention (main + ip), fused
    attn_kernel<<<dim3(S1_ / 64, H_, B_), 64>>>();

    // Output projection (src: g_CTX, dst: harness d_out)
    sgemm128<<<dim3(HID_ / 128, M1 / 128), 256>>>(nullptr, wo, bo, (float*)d_out, M1, HID_, HID_, 3, -1);
}

// round 4
// speedup vs baseline: 1.5293x; 1.5293x over previous
#include <cuda_runtime.h>
#include <cuda_bf16.h>
#include <math.h>
#include <stdint.h>

// Problem constants
#define B_   8
#define S1_  4096
#define S2_  256
#define SIP_ 16
#define HID_ 1024
#define H_   16
#define D_   64

// ---------------------------------------------------------------------------
// Scratch: static __device__ globals (no cudaMalloc anywhere, per harness rules)
// ---------------------------------------------------------------------------
__device__ float g_Q   [(size_t)B_ * S1_ * HID_];        // [B,S1,H,D] after LN+RoPE
__device__ float g_KV  [(size_t)B_ * S2_ * 2 * HID_];    // [B,S2,2,H,D], k LN'd in place
__device__ float g_IPKV[(size_t)B_ * SIP_ * 2 * HID_];   // [B,SIP,2,H,D]
__device__ float g_CTX [(size_t)B_ * S1_ * HID_];        // [B,S1,H,D]

__device__ __forceinline__ float* scratch_ptr(int which) {
    switch (which) {
        case 0: return g_Q;
        case 1: return g_KV;
        case 2: return g_IPKV;
        default: return g_CTX;
    }
}

// fp32 -> tf32 (round-to-nearest; unbiased, eps ~ 2^-11)
__device__ __forceinline__ uint32_t f2tf32(float x) {
    uint32_t r;
    asm("cvt.rna.tf32.f32 %0, %1;" : "=r"(r) : "f"(x));
    return r;
}

__device__ __forceinline__ void mma_tf32(
    float& c0, float& c1, float& c2, float& c3,
    uint32_t a0, uint32_t a1, uint32_t a2, uint32_t a3,
    uint32_t b0, uint32_t b1)
{
    asm volatile(
        "mma.sync.aligned.m16n8k8.row.col.f32.tf32.tf32.f32 "
        "{%0,%1,%2,%3}, {%4,%5,%6,%7}, {%8,%9}, {%0,%1,%2,%3};\n"
        : "+f"(c0), "+f"(c1), "+f"(c2), "+f"(c3)
        : "r"(a0), "r"(a1), "r"(a2), "r"(a3), "r"(b0), "r"(b1));
}

// ---------------------------------------------------------------------------
// TF32 tensor-core GEMM: C[M,N] = A[M,K] @ B[K,N] + bias[N]  (row-major)
// Block tile 128x128, BK=16, 256 threads = 8 warps (4M x 2N), warp tile 32x64.
// mma.sync.m16n8k8.tf32, fp32 accumulate. Register double-buffered staging
// with cvt.rna at store time. Requires M%128==0, N%128==0, K%16==0.
// ---------------------------------------------------------------------------
#define APAD 20    // A smem row stride (floats): 16 payload + 4 pad
#define BPAD 132   // B smem row stride (floats): 128 payload + 4 pad

__global__ __launch_bounds__(256) void gemm_tf32(
    const float* __restrict__ Ain, const float* __restrict__ Bm,
    const float* __restrict__ bias, float* __restrict__ Cout,
    int M, int N, int K, int srcSel, int dstSel)
{
    const float* A = (srcSel < 0) ? Ain : scratch_ptr(srcSel);
    float*       C = (dstSel < 0) ? Cout : scratch_ptr(dstSel);

    __shared__ uint32_t As[2][128 * APAD];   // 2 * 10240 B
    __shared__ uint32_t Bs[2][16 * BPAD];    // 2 *  8448 B

    const int tid  = threadIdx.x;
    const int lane = tid & 31;
    const int warp = tid >> 5;
    const int wm   = warp >> 1;          // 0..3  (M dir)
    const int wn   = warp & 1;           // 0..1  (N dir)
    const int g    = lane >> 2;          // groupID 0..7
    const int tg   = lane & 3;           // thread-in-group 0..3

    const int bxBase = blockIdx.x * 128; // N offset
    const int byBase = blockIdx.y * 128; // M offset

    // staging indices
    const int arow = tid >> 1;           // 0..127
    const int acol = (tid & 1) * 8;      // 0 or 8
    const int brow = tid >> 4;           // 0..15
    const int bcol = (tid & 15) * 8;     // 0..120

    const float* Ag = A  + (size_t)(byBase + arow) * K + acol;
    const float* Bg = Bm + (size_t)brow * N + bxBase + bcol;

    float acc[2][8][4];
#pragma unroll
    for (int mi = 0; mi < 2; mi++)
#pragma unroll
        for (int ni = 0; ni < 8; ni++)
#pragma unroll
            for (int c = 0; c < 4; c++) acc[mi][ni][c] = 0.f;

    const int iters = K / 16;

    // prologue: tile 0
    float4 ra0 = *(const float4*)(Ag);
    float4 ra1 = *(const float4*)(Ag + 4);
    float4 rb0 = *(const float4*)(Bg);
    float4 rb1 = *(const float4*)(Bg + 4);
    {
        uint32_t* ap = &As[0][arow * APAD + acol];
        ap[0] = f2tf32(ra0.x); ap[1] = f2tf32(ra0.y); ap[2] = f2tf32(ra0.z); ap[3] = f2tf32(ra0.w);
        ap[4] = f2tf32(ra1.x); ap[5] = f2tf32(ra1.y); ap[6] = f2tf32(ra1.z); ap[7] = f2tf32(ra1.w);
        uint32_t* bp = &Bs[0][brow * BPAD + bcol];
        bp[0] = f2tf32(rb0.x); bp[1] = f2tf32(rb0.y); bp[2] = f2tf32(rb0.z); bp[3] = f2tf32(rb0.w);
        bp[4] = f2tf32(rb1.x); bp[5] = f2tf32(rb1.y); bp[6] = f2tf32(rb1.z); bp[7] = f2tf32(rb1.w);
    }
    __syncthreads();

#pragma unroll 1
    for (int it = 0; it < iters; it++) {
        const int p = it & 1;

        // issue next-tile global loads early (hide latency behind mma)
        if (it + 1 < iters) {
            const float* Agn = Ag + (size_t)(it + 1) * 16;
            const float* Bgn = Bg + (size_t)(it + 1) * 16 * N;
            ra0 = *(const float4*)(Agn);
            ra1 = *(const float4*)(Agn + 4);
            rb0 = *(const float4*)(Bgn);
            rb1 = *(const float4*)(Bgn + 4);
        }

        // compute current tile
        const uint32_t* Ab = &As[p][0];
        const uint32_t* Bb = &Bs[p][0];
#pragma unroll
        for (int kc = 0; kc < 2; kc++) {
            const int k0 = kc * 8;
            // B fragments: 8 n-tiles x 2 regs
            uint32_t bf[8][2];
#pragma unroll
            for (int ni = 0; ni < 8; ni++) {
                const int n = wn * 64 + ni * 8 + g;
                bf[ni][0] = Bb[(k0 + tg)     * BPAD + n];
                bf[ni][1] = Bb[(k0 + tg + 4) * BPAD + n];
            }
            // A fragments: 2 m-tiles x 4 regs
            uint32_t af[2][4];
#pragma unroll
            for (int mi = 0; mi < 2; mi++) {
                const int r = wm * 32 + mi * 16 + g;
                af[mi][0] = Ab[r       * APAD + k0 + tg];
                af[mi][1] = Ab[(r + 8) * APAD + k0 + tg];
                af[mi][2] = Ab[r       * APAD + k0 + tg + 4];
                af[mi][3] = Ab[(r + 8) * APAD + k0 + tg + 4];
            }
#pragma unroll
            for (int mi = 0; mi < 2; mi++)
#pragma unroll
                for (int ni = 0; ni < 8; ni++)
                    mma_tf32(acc[mi][ni][0], acc[mi][ni][1], acc[mi][ni][2], acc[mi][ni][3],
                             af[mi][0], af[mi][1], af[mi][2], af[mi][3],
                             bf[ni][0], bf[ni][1]);
        }

        // stage next tile into the other buffer
        if (it + 1 < iters) {
            const int q = (it + 1) & 1;
            uint32_t* ap = &As[q][arow * APAD + acol];
            ap[0] = f2tf32(ra0.x); ap[1] = f2tf32(ra0.y); ap[2] = f2tf32(ra0.z); ap[3] = f2tf32(ra0.w);
            ap[4] = f2tf32(ra1.x); ap[5] = f2tf32(ra1.y); ap[6] = f2tf32(ra1.z); ap[7] = f2tf32(ra1.w);
            uint32_t* bp = &Bs[q][brow * BPAD + bcol];
            bp[0] = f2tf32(rb0.x); bp[1] = f2tf32(rb0.y); bp[2] = f2tf32(rb0.z); bp[3] = f2tf32(rb0.w);
            bp[4] = f2tf32(rb1.x); bp[5] = f2tf32(rb1.y); bp[6] = f2tf32(rb1.z); bp[7] = f2tf32(rb1.w);
        }
        __syncthreads();
    }

    // epilogue: bias add + direct stores (float2 per fragment row)
#pragma unroll
    for (int ni = 0; ni < 8; ni++) {
        const int col = bxBase + wn * 64 + ni * 8 + tg * 2;
        const float2 bb = *(const float2*)&bias[col];
#pragma unroll
        for (int mi = 0; mi < 2; mi++) {
            const int row0 = byBase + wm * 32 + mi * 16 + g;
            float2 v0, v1;
            v0.x = acc[mi][ni][0] + bb.x; v0.y = acc[mi][ni][1] + bb.y;
            v1.x = acc[mi][ni][2] + bb.x; v1.y = acc[mi][ni][3] + bb.y;
            *(float2*)&C[(size_t)row0 * N + col]       = v0;
            *(float2*)&C[(size_t)(row0 + 8) * N + col] = v1;
        }
    }
}

// ---------------------------------------------------------------------------
// LayerNorm(D=64) + RoPE on g_Q, in place. One warp per (b,s,h) row.
// ---------------------------------------------------------------------------
__global__ __launch_bounds__(128) void ln_rope_q_kernel(
    const float* __restrict__ w, const float* __restrict__ bb,
    const float* __restrict__ cosb, const float* __restrict__ sinb)
{
    const int row  = blockIdx.x * 4 + (threadIdx.x >> 5);   // 0 .. B*S1*H-1
    const int lane = threadIdx.x & 31;
    const int s    = (row >> 4) & (S1_ - 1);                // row = (b*S1+s)*H + h

    float2* p = (float2*)(g_Q + (size_t)row * 64);
    float2 v = p[lane];

    float sum = v.x + v.y;
#pragma unroll
    for (int o = 16; o; o >>= 1) sum += __shfl_xor_sync(0xffffffffu, sum, o);
    float mu = sum * (1.f / 64.f);

    float dx = v.x - mu, dy = v.y - mu;
    float ss = dx * dx + dy * dy;
#pragma unroll
    for (int o = 16; o; o >>= 1) ss += __shfl_xor_sync(0xffffffffu, ss, o);
    float r = rsqrtf(ss * (1.f / 64.f) + 1e-6f);

    float nx = dx * r * w[2 * lane]     + bb[2 * lane];
    float ny = dy * r * w[2 * lane + 1] + bb[2 * lane + 1];

    float c  = cosb[s * 32 + lane];
    float sn = sinb[s * 32 + lane];
    float2 o2;
    o2.x = nx * c - ny * sn;
    o2.y = nx * sn + ny * c;
    p[lane] = o2;
}

// ---------------------------------------------------------------------------
// LayerNorm(D=64) on the K half of g_KV (sel=1) or g_IPKV (sel=2), in place.
// ---------------------------------------------------------------------------
__global__ __launch_bounds__(128) void ln_k_kernel(
    const float* __restrict__ w, const float* __restrict__ bb, int sel)
{
    float* KV = scratch_ptr(sel);
    const int row  = blockIdx.x * 4 + (threadIdx.x >> 5);
    const int lane = threadIdx.x & 31;
    const int h  = row & 15;
    const int bs = row >> 4;

    float2* p = (float2*)(KV + (size_t)bs * 2048 + h * 64);
    float2 v = p[lane];

    float sum = v.x + v.y;
#pragma unroll
    for (int o = 16; o; o >>= 1) sum += __shfl_xor_sync(0xffffffffu, sum, o);
    float mu = sum * (1.f / 64.f);

    float dx = v.x - mu, dy = v.y - mu;
    float ss = dx * dx + dy * dy;
#pragma unroll
    for (int o = 16; o; o >>= 1) ss += __shfl_xor_sync(0xffffffffu, ss, o);
    float r = rsqrtf(ss * (1.f / 64.f) + 1e-6f);

    float2 o2;
    o2.x = dx * r * w[2 * lane]     + bb[2 * lane];
    o2.y = dy * r * w[2 * lane + 1] + bb[2 * lane + 1];
    p[lane] = o2;
}

// ---------------------------------------------------------------------------
// Fused dual attention (unchanged from passing round).
// ---------------------------------------------------------------------------
template <int KT>
__device__ __forceinline__ void attn_tile(
    const float4 q[16],
    const float* __restrict__ Kbase, const float* __restrict__ Vbase,
    float* Ks, float* Vs, float* Ss, int t,
    float& m, float& l, float acc[64])
{
    if (t < KT) {
        const float4* kp = (const float4*)(Kbase + (size_t)t * 2048);
        const float4* vp = (const float4*)(Vbase + (size_t)t * 2048);
        float4* kd = (float4*)(Ks + t * 64);
        float4* vd = (float4*)(Vs + t * 64);
#pragma unroll
        for (int i = 0; i < 16; i++) { kd[i] = kp[i]; vd[i] = vp[i]; }
    }
    __syncthreads();

    float tmax = -1e30f;
#pragma unroll 2
    for (int j = 0; j < KT; j++) {
        const float4* kr = (const float4*)(Ks + j * 64);
        float s0 = 0.f, s1 = 0.f, s2 = 0.f, s3 = 0.f;
#pragma unroll
        for (int i = 0; i < 4; i++) {
            float4 k0 = kr[4 * i + 0], k1 = kr[4 * i + 1];
            float4 k2 = kr[4 * i + 2], k3 = kr[4 * i + 3];
            float4 q0 = q[4 * i + 0], q1 = q[4 * i + 1];
            float4 q2 = q[4 * i + 2], q3 = q[4 * i + 3];
            s0 += q0.x * k0.x + q0.y * k0.y + q0.z * k0.z + q0.w * k0.w;
            s1 += q1.x * k1.x + q1.y * k1.y + q1.z * k1.z + q1.w * k1.w;
            s2 += q2.x * k2.x + q2.y * k2.y + q2.z * k2.z + q2.w * k2.w;
            s3 += q3.x * k3.x + q3.y * k3.y + q3.z * k3.z + q3.w * k3.w;
        }
        float sc = ((s0 + s1) + (s2 + s3)) * 0.125f;  // 1/sqrt(64)
        Ss[t * 64 + ((j + t) & 63)] = sc;             // swizzled: conflict-free
        tmax = fmaxf(tmax, sc);
    }

    float mn = fmaxf(m, tmax);
    float corr = __expf(m - mn);
    l *= corr;
#pragma unroll
    for (int d = 0; d < 64; d++) acc[d] *= corr;
    m = mn;

#pragma unroll 2
    for (int j = 0; j < KT; j++) {
        float p = __expf(Ss[t * 64 + ((j + t) & 63)] - m);
        l += p;
        const float4* vr = (const float4*)(Vs + j * 64);
#pragma unroll
        for (int i = 0; i < 16; i++) {
            float4 v4 = vr[i];
            acc[4 * i + 0] += p * v4.x;
            acc[4 * i + 1] += p * v4.y;
            acc[4 * i + 2] += p * v4.z;
            acc[4 * i + 3] += p * v4.w;
        }
    }
    __syncthreads();
}

__global__ __launch_bounds__(64) void attn_kernel()
{
    __shared__ float Ks[64 * 64];
    __shared__ float Vs[64 * 64];
    __shared__ float Ss[64 * 64];

    const int qt = blockIdx.x;   // S1/64 tiles
    const int h  = blockIdx.y;
    const int b  = blockIdx.z;
    const int t  = threadIdx.x;

    const size_t qrow = (size_t)(b * S1_ + qt * 64 + t) * H_ + h;
    float4 q[16];
    const float4* qp = (const float4*)(g_Q + qrow * 64);
#pragma unroll
    for (int i = 0; i < 16; i++) q[i] = qp[i];

    float m = -1e30f, l = 0.f, acc[64];
#pragma unroll
    for (int d = 0; d < 64; d++) acc[d] = 0.f;

    // main attention: 256 keys in 4 tiles of 64
    for (int kt = 0; kt < 4; kt++) {
        const float* kb = g_KV + (size_t)(b * S2_ + kt * 64) * 2048 + h * 64;
        attn_tile<64>(q, kb, kb + 1024, Ks, Vs, Ss, t, m, l, acc);
    }
    float inv = 1.f / l;
    float4* cp = (float4*)(g_CTX + qrow * 64);
#pragma unroll
    for (int i = 0; i < 16; i++)
        cp[i] = make_float4(acc[4 * i] * inv, acc[4 * i + 1] * inv,
                            acc[4 * i + 2] * inv, acc[4 * i + 3] * inv);

    // ip attention: 16 keys, separate softmax
    m = -1e30f; l = 0.f;
#pragma unroll
    for (int d = 0; d < 64; d++) acc[d] = 0.f;
    {
        const float* kb = g_IPKV + (size_t)(b * SIP_) * 2048 + h * 64;
        attn_tile<16>(q, kb, kb + 1024, Ks, Vs, Ss, t, m, l, acc);
    }
    inv = 1.f / l;
#pragma unroll
    for (int i = 0; i < 16; i++) {
        float4 c = cp[i];
        c.x += acc[4 * i + 0] * inv;
        c.y += acc[4 * i + 1] * inv;
        c.z += acc[4 * i + 2] * inv;
        c.w += acc[4 * i + 3] * inv;
        cp[i] = c;
    }
}

// ---------------------------------------------------------------------------
// Launch: pure kernel launches only.
// ---------------------------------------------------------------------------
extern "C" void kernel_launch(void* const* d_in, const int* in_sizes, int n_in,
                              void* d_out, int out_size)
{
    const float *x, *y, *ipy, *fcos, *fsin, *wq, *bq, *wkv, *bkv, *wip, *bip;
    const float *qnw, *qnb, *knw, *knb, *ipknw, *ipknb, *wo, *bo;

    if (in_sizes[3] == 131072) {
        // reference-signature order
        x    = (const float*)d_in[0];  y     = (const float*)d_in[1];
        ipy  = (const float*)d_in[2];  fcos  = (const float*)d_in[3];
        fsin = (const float*)d_in[4];  wq    = (const float*)d_in[5];
        bq   = (const float*)d_in[6];  wkv   = (const float*)d_in[7];
        bkv  = (const float*)d_in[8];  wip   = (const float*)d_in[9];
        bip  = (const float*)d_in[10]; qnw   = (const float*)d_in[11];
        qnb  = (const float*)d_in[12]; knw   = (const float*)d_in[13];
        knb  = (const float*)d_in[14]; ipknw = (const float*)d_in[15];
        ipknb= (const float*)d_in[16]; wo    = (const float*)d_in[17];
        bo   = (const float*)d_in[18];
    } else {
        // setup_inputs dict order
        x    = (const float*)d_in[0];  y     = (const float*)d_in[1];
        ipy  = (const float*)d_in[2];  wq    = (const float*)d_in[3];
        bq   = (const float*)d_in[4];  wkv   = (const float*)d_in[5];
        bkv  = (const float*)d_in[6];  wip   = (const float*)d_in[7];
        bip  = (const float*)d_in[8];  qnw   = (const float*)d_in[9];
        qnb  = (const float*)d_in[10]; knw   = (const float*)d_in[11];
        knb  = (const float*)d_in[12]; ipknw = (const float*)d_in[13];
        ipknb= (const float*)d_in[14]; wo    = (const float*)d_in[15];
        bo   = (const float*)d_in[16]; fcos  = (const float*)d_in[17];
        fsin = (const float*)d_in[18];
    }

    const int M1 = B_ * S1_;     // 32768
    const int M2 = B_ * S2_;     // 2048
    const int M3 = B_ * SIP_;    // 128

    // Projections (dst: 0=g_Q, 1=g_KV, 2=g_IPKV, 3=g_CTX)
    gemm_tf32<<<dim3(HID_ / 128, M1 / 128), 256>>>(x,   wq,  bq,  nullptr, M1, HID_,     HID_, -1, 0);
    gemm_tf32<<<dim3(2 * HID_ / 128, M2 / 128), 256>>>(y,   wkv, bkv, nullptr, M2, 2 * HID_, HID_, -1, 1);
    gemm_tf32<<<dim3(2 * HID_ / 128, M3 / 128), 256>>>(ipy, wip, bip, nullptr, M3, 2 * HID_, HID_, -1, 2);

    // Norms + RoPE
    ln_rope_q_kernel<<<(B_ * S1_ * H_) / 4, 128>>>(qnw, qnb, fcos, fsin);
    ln_k_kernel<<<(B_ * S2_ * H_) / 4, 128>>>(knw, knb, 1);
    ln_k_kernel<<<(B_ * SIP_ * H_) / 4, 128>>>(ipknw, ipknb, 2);

    // Dual attention (main + ip), fused
    attn_kernel<<<dim3(S1_ / 64, H_, B_), 64>>>();

    // Output projection (src: g_CTX, dst: harness d_out)
    gemm_tf32<<<dim3(HID_ / 128, M1 / 128), 256>>>(nullptr, wo, bo, (float*)d_out, M1, HID_, HID_, 3, -1);
}